// round 9
// baseline (speedup 1.0000x reference)
#include <cuda_runtime.h>
#include <cuda_fp16.h>
#include <cstdint>

#define BATCH 4096
#define NA 8
#define ND 11
#define NPOS 3584
#define ATOM 512
#define NS 4096
#define ROWS 32768          // BATCH*NA
#define NTILES 448          // NPOS/8
#define EPS 2.5e-3f         // > 2 * fp16-coarse sim error (~1e-3)
#define QCHUNK 896          // NPOS/4, fixup SMEM chunk

__device__ uint2 g_Bfh[NTILES * 32];     // B hi fragments
__device__ float g_Bn[NPOS * 12];        // exact normalized positions (pad 12)
__device__ unsigned long long g_keyC[ROWS];  // coarse keys (plain store)
__device__ unsigned long long g_keyE[ROWS];  // exact keys (fixup, atomicMax)
__device__ int g_flag[ROWS];
__device__ int g_queue[ROWS];
__device__ int g_qn;

static __device__ __forceinline__ uint32_t h2pack(float x, float y) {
    __half2 h = __halves2half2(__float2half_rn(x), __float2half_rn(y));
    return *(uint32_t*)&h;
}
static __device__ __forceinline__ unsigned long long mkkey(float s, int pos) {
    unsigned u = __float_as_uint(s);
    u = (u & 0x80000000u) ? ~u : (u | 0x80000000u);
    return ((unsigned long long)u << 32) | (unsigned)(NPOS - 1 - pos);
}

// ---- Phase 0: B-hi fragments, exact B table, zero state, passthrough ----
__global__ void prep_kernel(const float* __restrict__ index, const float* __restrict__ positions,
                            float* __restrict__ out_pass) {
    int t = blockIdx.x * blockDim.x + threadIdx.x;
    if (t == 0) g_qn = 0;
    if (t < ROWS) { g_keyE[t] = 0ull; g_flag[t] = 0; }
    if (t < NTILES * 32) {  // B fragments (4 tig lanes redundantly normalize one position)
        int lane = t & 31;
        int g = lane >> 2, tig = lane & 3;
        int p = (t >> 5) * 8 + g;
        const float* pp = positions + (size_t)p * ND;
        float v[ND], acc = 0.0f;
#pragma unroll
        for (int d = 0; d < ND; d++) { v[d] = pp[d]; acc = fmaf(v[d], v[d], acc); }
        float nrm = sqrtf(acc);
        float h[16];
#pragma unroll
        for (int d = 0; d < 16; d++) h[d] = (d < ND) ? (v[d] / nrm) : 0.0f;
        if (tig == 0) {
            float* bn = g_Bn + (size_t)p * 12;
#pragma unroll
            for (int d = 0; d < ND; d++) bn[d] = h[d];
            bn[11] = 0.0f;
        }
        int k0 = tig * 2;
        g_Bfh[t] = make_uint2(h2pack(h[k0], h[k0 + 1]), h2pack(h[k0 + 8], h[k0 + 9]));
    } else if (t < NTILES * 32 + ROWS * ND / 4) {  // passthrough (float4)
        int i = t - NTILES * 32;
        ((float4*)out_pass)[i] = ((const float4*)index)[i];
    }
}

static __device__ __forceinline__ void mma16816(float d[4], const uint4& a, uint32_t b0,
                                                uint32_t b1, const float c[4]) {
    asm volatile(
        "mma.sync.aligned.m16n8k16.row.col.f32.f16.f16.f32 "
        "{%0,%1,%2,%3}, {%4,%5,%6,%7}, {%8,%9}, {%10,%11,%12,%13};"
        : "=f"(d[0]), "=f"(d[1]), "=f"(d[2]), "=f"(d[3])
        : "r"(a.x), "r"(a.y), "r"(a.z), "r"(a.w), "r"(b0), "r"(b1),
          "f"(c[0]), "f"(c[1]), "f"(c[2]), "f"(c[3]));
}

// ---- Phase 1: 1-HMMA coarse argmax with conservative near-tie flagging ----
__global__ void __launch_bounds__(256, 1) argmax_kernel(const float* __restrict__ index) {
    extern __shared__ uint2 sB[];           // 448*32*8 = 114688 B
    __shared__ float sAn[128][16];          // normalized A rows, padded

    const int tid = threadIdx.x;
    const int lane = tid & 31;
    const int wid = tid >> 5;
    const int g = lane >> 2, tig = lane & 3;

    {   // cooperative B fill
        const uint4* src = (const uint4*)g_Bfh;
        uint4* dst = (uint4*)sB;
        for (int i = tid; i < NTILES * 16; i += 256) dst[i] = src[i];
    }
    if (tid < 128) {  // normalize this CTA's 128 A rows (reference op order)
        int row = blockIdx.x * 128 + tid;
        const float* ip = index + (size_t)row * ND;
        float v[ND], acc = 0.0f;
#pragma unroll
        for (int d = 0; d < ND; d++) { v[d] = ip[d]; acc = fmaf(v[d], v[d], acc); }
        float nrm = sqrtf(acc);
#pragma unroll
        for (int d = 0; d < 16; d++) sAn[tid][d] = (d < ND) ? (v[d] / nrm) : 0.0f;
    }
    __syncthreads();

    // build Ah fragment for this lane
    const float* A0 = sAn[wid * 16 + g];
    const float* A1 = sAn[wid * 16 + g + 8];
    const int k0 = tig * 2;
    uint4 Ah = make_uint4(h2pack(A0[k0], A0[k0 + 1]), h2pack(A1[k0], A1[k0 + 1]),
                          h2pack(A0[k0 + 8], A0[k0 + 9]), h2pack(A1[k0 + 8], A1[k0 + 9]));

    const float zc[4] = {0.f, 0.f, 0.f, 0.f};
    float best0 = -1e30f, best1 = -1e30f;
    int bi0 = 0, bi1 = 0;
    bool fl0 = false, fl1 = false;

#pragma unroll 2
    for (int t = 0; t < NTILES; t += 2) {
        uint2 B0 = sB[t * 32 + lane];
        uint2 B1 = sB[(t + 1) * 32 + lane];
        float d0[4], d1[4];
        mma16816(d0, Ah, B0.x, B0.y, zc);
        mma16816(d1, Ah, B1.x, B1.y, zc);
        int p = t * 8 + tig * 2;

        {   // row0: candidates d0[0],d0[1],d1[0],d1[1] at p,p+1,p+8,p+9
            float a = fmaxf(d0[0], d0[1]), b = fminf(d0[0], d0[1]);
            float c = fmaxf(d1[0], d1[1]), dd = fminf(d1[0], d1[1]);
            float m = fmaxf(a, c);
            float r2 = fmaxf(fminf(a, c), (a > c) ? b : dd);  // runner-up of 4
            bool upd = (m > best0);
            float tt = upd ? fmaxf(best0, r2) : m;
            float ref = upd ? m : best0;
            fl0 = fl0 || (tt > ref - EPS);
            if (upd) {
                best0 = m;
                bi0 = (m == d0[0]) ? p : (m == d0[1]) ? p + 1 : (m == d1[0]) ? p + 8 : p + 9;
            }
        }
        {   // row1
            float a = fmaxf(d0[2], d0[3]), b = fminf(d0[2], d0[3]);
            float c = fmaxf(d1[2], d1[3]), dd = fminf(d1[2], d1[3]);
            float m = fmaxf(a, c);
            float r2 = fmaxf(fminf(a, c), (a > c) ? b : dd);
            bool upd = (m > best1);
            float tt = upd ? fmaxf(best1, r2) : m;
            float ref = upd ? m : best1;
            fl1 = fl1 || (tt > ref - EPS);
            if (upd) {
                best1 = m;
                bi1 = (m == d0[2]) ? p : (m == d0[3]) ? p + 1 : (m == d1[2]) ? p + 8 : p + 9;
            }
        }
    }

    // reduce over the 4 tig lanes of each row
    unsigned long long k0v = mkkey(best0, bi0), k1v = mkkey(best1, bi1);
    int f0 = fl0 ? 1 : 0, f1 = fl1 ? 1 : 0;
#pragma unroll
    for (int s = 1; s <= 2; s <<= 1) {
        unsigned long long o0 = __shfl_xor_sync(0xFFFFFFFFu, k0v, s);
        unsigned long long o1 = __shfl_xor_sync(0xFFFFFFFFu, k1v, s);
        if (o0 > k0v) k0v = o0;
        if (o1 > k1v) k1v = o1;
        f0 += __shfl_xor_sync(0xFFFFFFFFu, f0, s);
        f1 += __shfl_xor_sync(0xFFFFFFFFu, f1, s);
    }
    // cross-lane near-tie: >=2 lanes within EPS of global best
    float bg0 = __uint_as_float(((unsigned)(k0v >> 32) & 0x80000000u)
                    ? ((unsigned)(k0v >> 32) & 0x7FFFFFFFu) : ~(unsigned)(k0v >> 32));
    float bg1 = __uint_as_float(((unsigned)(k1v >> 32) & 0x80000000u)
                    ? ((unsigned)(k1v >> 32) & 0x7FFFFFFFu) : ~(unsigned)(k1v >> 32));
    int n0 = (best0 > bg0 - EPS) ? 1 : 0;
    int n1 = (best1 > bg1 - EPS) ? 1 : 0;
#pragma unroll
    for (int s = 1; s <= 2; s <<= 1) {
        n0 += __shfl_xor_sync(0xFFFFFFFFu, n0, s);
        n1 += __shfl_xor_sync(0xFFFFFFFFu, n1, s);
    }
    if (tig == 0) {
        int row0 = blockIdx.x * 128 + wid * 16 + g;
        int row1 = row0 + 8;
        g_keyC[row0] = k0v;
        g_keyC[row1] = k1v;
        if (f0 > 0 || n0 >= 2) {
            g_flag[row0] = 1;
            g_queue[atomicAdd(&g_qn, 1)] = row0;
        }
        if (f1 > 0 || n1 >= 2) {
            g_flag[row1] = 1;
            g_queue[atomicAdd(&g_qn, 1)] = row1;
        }
    }
}

// ---- Phase 1b: exact fp32 re-scan of flagged rows, B chunked in SMEM ----
__global__ void __launch_bounds__(256) fixup_kernel(const float* __restrict__ index) {
    __shared__ float sBn[12 * QCHUNK];  // transposed [d][pos], 43008 B
    const int tid = threadIdx.x;
    const int lane = tid & 31;
    const int wid = tid >> 5;
    const int chunk = blockIdx.x & 3;
    const int p0 = chunk * QCHUNK;

    for (int i = tid; i < QCHUNK * 12; i += 256) {
        int pos = i / 12, d = i % 12;
        sBn[d * QCHUNK + pos] = g_Bn[(size_t)(p0 + pos) * 12 + d];
    }
    __syncthreads();

    const int qn = g_qn;
    for (int qi = (blockIdx.x >> 2) * 8 + wid; qi < qn; qi += (gridDim.x >> 2) * 8) {
        int row = g_queue[qi];
        const float* ip = index + (size_t)row * ND;
        float a[ND], acc = 0.0f;
#pragma unroll
        for (int d = 0; d < ND; d++) { a[d] = ip[d]; acc = fmaf(a[d], a[d], acc); }
        float nrm = sqrtf(acc);
#pragma unroll
        for (int d = 0; d < ND; d++) a[d] = a[d] / nrm;

        unsigned long long key = 0ull;
        for (int j = 0; j < QCHUNK / 32; j++) {
            int pl = lane + j * 32;
            float s = a[0] * sBn[pl];
#pragma unroll
            for (int d = 1; d < ND; d++) s = fmaf(a[d], sBn[d * QCHUNK + pl], s);
            unsigned long long k = mkkey(s, p0 + pl);
            if (k > key) key = k;
        }
#pragma unroll
        for (int s = 1; s <= 16; s <<= 1) {
            unsigned long long o = __shfl_xor_sync(0xFFFFFFFFu, key, s);
            if (o > key) key = o;
        }
        if (lane == 0) atomicMax(&g_keyE[row], key);
    }
}

// ---- Phase 2: register-direct scatter + int_index write ----
__global__ void __launch_bounds__(1024) scatter_kernel(const float* __restrict__ atoms,
                                                       float* __restrict__ out) {
    __shared__ int offs[NA];
    const int b = blockIdx.x;
    const int tid = threadIdx.x;
    if (tid < NA) {
        int row = b * NA + tid;
        unsigned long long k = g_flag[row] ? g_keyE[row] : g_keyC[row];
        int idx = NPOS - 1 - (int)(unsigned)(k & 0xFFFFFFFFull);
        offs[tid] = idx;
        out[row] = (float)idx;  // int_index section
    }
    __syncthreads();

    const int s0 = tid * 4;
    float v0 = 0.f, v1 = 0.f, v2 = 0.f, v3 = 0.f;
#pragma unroll
    for (int a = 0; a < NA; a++) {
        int t0 = s0 - offs[a];
        if ((unsigned)(t0 + 3) < (unsigned)(ATOM + 3)) {
            const float* ap = atoms + a * ATOM;
            if ((unsigned)t0 < (unsigned)ATOM) v0 += __ldg(ap + t0);
            if ((unsigned)(t0 + 1) < (unsigned)ATOM) v1 += __ldg(ap + t0 + 1);
            if ((unsigned)(t0 + 2) < (unsigned)ATOM) v2 += __ldg(ap + t0 + 2);
            if ((unsigned)(t0 + 3) < (unsigned)ATOM) v3 += __ldg(ap + t0 + 3);
        }
    }
    *(float4*)(out + ROWS + (size_t)b * NS + s0) = make_float4(v0, v1, v2, v3);
}

extern "C" void kernel_launch(void* const* d_in, const int* in_sizes, int n_in,
                              void* d_out, int out_size) {
    const float* index = (const float*)d_in[0];      // (4096, 8, 11)
    const float* positions = (const float*)d_in[1];  // (3584, 11)
    const float* atoms = (const float*)d_in[2];      // (8, 512)
    float* out = (float*)d_out;  // [int_index(32768) | output(16777216) | index(360448)]

    const int prep_threads = NTILES * 32 + ROWS * ND / 4;  // 104448
    prep_kernel<<<(prep_threads + 255) / 256, 256>>>(
        index, positions, out + ROWS + (size_t)BATCH * NS);

    const int smem = NTILES * 32 * sizeof(uint2);  // 114688 B
    cudaFuncSetAttribute(argmax_kernel, cudaFuncAttributeMaxDynamicSharedMemorySize, smem);
    argmax_kernel<<<ROWS / 128, 256, smem>>>(index);

    fixup_kernel<<<256, 256>>>(index);

    scatter_kernel<<<BATCH, 1024>>>(atoms, out);
}

// round 10
// speedup vs baseline: 3.6746x; 3.6746x over previous
#include <cuda_runtime.h>
#include <cuda_fp16.h>
#include <cstdint>

#define BATCH 4096
#define NA 8
#define ND 11
#define NPOS 3584
#define ATOM 512
#define NS 4096
#define ROWS 32768          // BATCH*NA
#define NTILES 448          // NPOS/8
#define NRB 2048            // ROWS/16 row-blocks
#define HTILES 224          // tiles per position-half
#define CTILES 32           // tiles per SMEM chunk (16 KB)
#define NCHH 7              // HTILES/CTILES
#define INV4096 (1.0f/4096.0f)

__device__ uint4 g_Bf[NTILES * 32];          // B fragments {b0h,b1h,b0l,b1l}
__device__ unsigned long long g_key[ROWS];   // merged via atomicMax
__device__ int g_dummy;

static __device__ __forceinline__ uint32_t h2pack(float x, float y) {
    __half2 h = __halves2half2(__float2half_rn(x), __float2half_rn(y));
    return *(uint32_t*)&h;
}
static __device__ __forceinline__ uint32_t smem_u32(const void* p) {
    uint32_t a;
    asm("{ .reg .u64 t; cvta.to.shared.u64 t, %1; cvt.u32.u64 %0, t; }" : "=r"(a) : "l"(p));
    return a;
}
#define CP_ASYNC16(smem, gmem) \
    asm volatile("cp.async.cg.shared.global [%0], [%1], 16;" :: "r"(smem), "l"(gmem) : "memory")
#define CP_COMMIT() asm volatile("cp.async.commit_group;" ::: "memory")
#define CP_WAIT(n)  asm volatile("cp.async.wait_group %0;" :: "n"(n) : "memory")

// ---- Phase 0: B fragments (hi/lo), zero merge keys, raw-index passthrough ----
__global__ void prep_kernel(const float* __restrict__ index, const float* __restrict__ positions,
                            float* __restrict__ out_pass) {
    int t = blockIdx.x * blockDim.x + threadIdx.x;
    if (t < ROWS) g_key[t] = 0ull;
    if (t < NTILES * 32) {  // B fragments (4 tig lanes redundantly normalize one position)
        int lane = t & 31;
        int g = lane >> 2, tig = lane & 3;
        int p = (t >> 5) * 8 + g;
        const float* pp = positions + (size_t)p * ND;
        float v[ND], acc = 0.0f;
#pragma unroll
        for (int d = 0; d < ND; d++) { v[d] = pp[d]; acc = fmaf(v[d], v[d], acc); }
        float nrm = sqrtf(acc);
        float h[16], l[16];
#pragma unroll
        for (int d = 0; d < 16; d++) {
            float f = (d < ND) ? (v[d] / nrm) : 0.0f;
            float hi = __half2float(__float2half_rn(f));
            h[d] = hi;
            l[d] = (f - hi) * 4096.0f;
        }
        int k0 = tig * 2;
        g_Bf[t] = make_uint4(h2pack(h[k0], h[k0 + 1]), h2pack(h[k0 + 8], h[k0 + 9]),
                             h2pack(l[k0], l[k0 + 1]), h2pack(l[k0 + 8], l[k0 + 9]));
    }
    if (t < ROWS * ND / 4)  // passthrough (float4)
        ((float4*)out_pass)[t] = ((const float4*)index)[t];
}

static __device__ __forceinline__ void mma16816(float d[4], const uint4& a, uint32_t b0,
                                                uint32_t b1, const float c[4]) {
    asm volatile(
        "mma.sync.aligned.m16n8k16.row.col.f32.f16.f16.f32 "
        "{%0,%1,%2,%3}, {%4,%5,%6,%7}, {%8,%9}, {%10,%11,%12,%13};"
        : "=f"(d[0]), "=f"(d[1]), "=f"(d[2]), "=f"(d[3])
        : "r"(a.x), "r"(a.y), "r"(a.z), "r"(a.w), "r"(b0), "r"(b1),
          "f"(c[0]), "f"(c[1]), "f"(c[2]), "f"(c[3]));
}

// ---- Phase 1: split-fp16 mma GEMM (2-limb, 3 HMMA/tile) + streaming argmax.
// blockIdx = (row-block-octet, pos-half); A fragments built in-kernel. ----
__global__ void __launch_bounds__(256, 1) argmax_kernel(const float* __restrict__ index) {
    extern __shared__ uint4 sB[];       // [2][CTILES*32] = 32 KB
    __shared__ float sAn[128][16];      // normalized A rows (exact fp32)

    const int tid = threadIdx.x;
    const int lane = tid & 31;
    const int half = blockIdx.x & 1;
    const int rb8 = blockIdx.x >> 1;                 // row-block octet
    const int warp = (rb8 << 3) + (tid >> 5);        // row-block id
    const int g = lane >> 2, tig = lane & 3;
    const uint32_t sb0 = smem_u32(sB);

    const uint4* bsrc = g_Bf + (size_t)half * (HTILES * 32);

    {   // issue B chunk 0
#pragma unroll
        for (int i = 0; i < 4; i++) {
            int idx = tid + i * 256;
            CP_ASYNC16(sb0 + (uint32_t)idx * 16u, bsrc + idx);
        }
        CP_COMMIT();
    }

    if (tid < 128) {  // normalize this CTA's 128 A rows (reference op order)
        int row = rb8 * 128 + tid;
        const float* ip = index + (size_t)row * ND;
        float v[ND], acc = 0.0f;
#pragma unroll
        for (int d = 0; d < ND; d++) { v[d] = ip[d]; acc = fmaf(v[d], v[d], acc); }
        float nrm = sqrtf(acc);
#pragma unroll
        for (int d = 0; d < 16; d++) sAn[tid][d] = (d < ND) ? (v[d] / nrm) : 0.0f;
    }
    __syncthreads();

    // build Ah/Al fragments for this lane from the two rows it covers
    const int wloc = (tid >> 5) * 16 + g;
    const float* A0 = sAn[wloc];
    const float* A1 = sAn[wloc + 8];
    uint4 Ah, Al;
    {
        const int k0 = tig * 2;
        float a0h[4], a1h[4], a0l[4], a1l[4];
#pragma unroll
        for (int j = 0; j < 2; j++) {
            float f00 = A0[k0 + j], f01 = A0[k0 + 8 + j];
            float f10 = A1[k0 + j], f11 = A1[k0 + 8 + j];
            float h00 = __half2float(__float2half_rn(f00));
            float h01 = __half2float(__float2half_rn(f01));
            float h10 = __half2float(__float2half_rn(f10));
            float h11 = __half2float(__float2half_rn(f11));
            a0h[j] = h00; a0h[2 + j] = h01;
            a1h[j] = h10; a1h[2 + j] = h11;
            a0l[j] = (f00 - h00) * 4096.0f; a0l[2 + j] = (f01 - h01) * 4096.0f;
            a1l[j] = (f10 - h10) * 4096.0f; a1l[2 + j] = (f11 - h11) * 4096.0f;
        }
        Ah = make_uint4(h2pack(a0h[0], a0h[1]), h2pack(a1h[0], a1h[1]),
                        h2pack(a0h[2], a0h[3]), h2pack(a1h[2], a1h[3]));
        Al = make_uint4(h2pack(a0l[0], a0l[1]), h2pack(a1l[0], a1l[1]),
                        h2pack(a0l[2], a0l[3]), h2pack(a1l[2], a1l[3]));
    }

    float best0 = -1e30f, best1 = -1e30f;
    int bi0 = 0, bi1 = 0;
    const float zc[4] = {0.f, 0.f, 0.f, 0.f};

    for (int c = 0; c < NCHH; c++) {
        if (c + 1 < NCHH) {
            const uint4* src = bsrc + (size_t)(c + 1) * (CTILES * 32);
            uint32_t dst = sb0 + (uint32_t)(((c + 1) & 1) * (CTILES * 32) * 16);
#pragma unroll
            for (int i = 0; i < 4; i++) {
                int idx = tid + i * 256;
                CP_ASYNC16(dst + (uint32_t)idx * 16u, src + idx);
            }
            CP_COMMIT();
            CP_WAIT(1);
        } else {
            CP_WAIT(0);
        }
        __syncthreads();

        const uint4* bb = sB + (c & 1) * (CTILES * 32);
        int pbase = half * (HTILES * 8) + c * CTILES * 8 + tig * 2;
#pragma unroll 4
        for (int t = 0; t < CTILES; t++) {
            uint4 B = bb[t * 32 + lane];
            float dh[4], dl[4];
            mma16816(dh, Ah, B.x, B.y, zc);   // Ah*Bh
            mma16816(dl, Ah, B.z, B.w, zc);   // Ah*Bl
            mma16816(dl, Al, B.x, B.y, dl);   // + Al*Bh
            float s0 = fmaf(dl[0], INV4096, dh[0]);
            float s1 = fmaf(dl[1], INV4096, dh[1]);
            float s2 = fmaf(dl[2], INV4096, dh[2]);
            float s3 = fmaf(dl[3], INV4096, dh[3]);

            int p = pbase + t * 8;
            float m0 = fmaxf(s0, s1);
            if (m0 > best0) { best0 = m0; bi0 = (s1 > s0) ? p + 1 : p; }
            float m1 = fmaxf(s2, s3);
            if (m1 > best1) { best1 = m1; bi1 = (s3 > s2) ? p + 1 : p; }
        }
        __syncthreads();
    }

    // reduce across the 4 lanes sharing each row, then merge halves via atomicMax
    unsigned u0 = __float_as_uint(best0);
    u0 = (u0 & 0x80000000u) ? ~u0 : (u0 | 0x80000000u);
    unsigned u1 = __float_as_uint(best1);
    u1 = (u1 & 0x80000000u) ? ~u1 : (u1 | 0x80000000u);
    unsigned long long k0 = ((unsigned long long)u0 << 32) | (unsigned)(NPOS - 1 - bi0);
    unsigned long long k1 = ((unsigned long long)u1 << 32) | (unsigned)(NPOS - 1 - bi1);
#pragma unroll
    for (int s = 1; s <= 2; s <<= 1) {
        unsigned long long o0 = __shfl_xor_sync(0xFFFFFFFFu, k0, s);
        unsigned long long o1 = __shfl_xor_sync(0xFFFFFFFFu, k1, s);
        if (o0 > k0) k0 = o0;
        if (o1 > k1) k1 = o1;
    }
    if (tig == 0) {
        int row0 = warp * 16 + g;
        atomicMax(&g_key[row0], k0);
        atomicMax(&g_key[row0 + 8], k1);
    }
}

// ---- Phase 2: column-owner scatter. Thread t owns output column t across the
// 8 chunks of 512 (SMEM buf written only by its owner -> no races, no syncs in
// the atom loop, fully coalesced loads/stores). 4 batches per CTA. ----
__global__ void __launch_bounds__(512) scatter_kernel(const float* __restrict__ atoms,
                                                      float* __restrict__ out) {
    __shared__ float buf[NS];    // [8 chunks][512 columns]
    __shared__ int offs[NA];
    const int tid = threadIdx.x;

#pragma unroll 1
    for (int bi = 0; bi < 4; bi++) {
        const int b = blockIdx.x * 4 + bi;
        __syncthreads();  // prior batch finished reading offs
        if (tid < NA) {
            int row = b * NA + tid;
            unsigned long long k = g_key[row];
            int idx = NPOS - 1 - (int)(unsigned)(k & 0xFFFFFFFFull);
            offs[tid] = idx;
            out[row] = (float)idx;  // int_index section
        }
#pragma unroll
        for (int c = 0; c < 8; c++) buf[c * 512 + tid] = 0.0f;  // owner-only
        __syncthreads();  // offs visible

#pragma unroll
        for (int a = 0; a < NA; a++) {
            int off = offs[a];
            int c0 = off >> 9, r = off & 511;
            if (tid >= r)
                buf[c0 * 512 + tid] += __ldg(atoms + a * ATOM + tid - r);
            else
                buf[(c0 + 1) * 512 + tid] += __ldg(atoms + a * ATOM + 512 - r + tid);
        }

        float* ob = out + ROWS + (size_t)b * NS;
#pragma unroll
        for (int c = 0; c < 8; c++) ob[c * 512 + tid] = buf[c * 512 + tid];
    }
}

extern "C" void kernel_launch(void* const* d_in, const int* in_sizes, int n_in,
                              void* d_out, int out_size) {
    const float* index = (const float*)d_in[0];      // (4096, 8, 11)
    const float* positions = (const float*)d_in[1];  // (3584, 11)
    const float* atoms = (const float*)d_in[2];      // (8, 512)
    float* out = (float*)d_out;  // [int_index(32768) | output(16777216) | index(360448)]

    prep_kernel<<<(ROWS * ND / 4 + 255) / 256, 256>>>(
        index, positions, out + ROWS + (size_t)BATCH * NS);

    const int smem = 2 * CTILES * 32 * sizeof(uint4);  // 32768 B dynamic
    cudaFuncSetAttribute(argmax_kernel, cudaFuncAttributeMaxDynamicSharedMemorySize, smem);
    argmax_kernel<<<(NRB / 8) * 2, 256, smem>>>(index);

    scatter_kernel<<<BATCH / 4, 512>>>(atoms, out);
}

// round 11
// speedup vs baseline: 3.7364x; 1.0168x over previous
#include <cuda_runtime.h>
#include <cuda_fp16.h>
#include <cstdint>

#define BATCH 4096
#define NA 8
#define ND 11
#define NPOS 3584
#define ATOM 512
#define NS 4096
#define ROWS 32768          // BATCH*NA
#define NTILES 448          // NPOS/8
#define NRB 2048            // ROWS/16 row-blocks
#define HTILES 224          // tiles per position-half
#define CTILES 32           // tiles per SMEM chunk
#define NCHH 7              // HTILES/CTILES
#define FRAG_B (CTILES * 32 * 16)      // 16384 B fragments per chunk
#define BL10_B (CTILES * 4 * 8)        // 1024 B bl10 per chunk
#define CHUNK_B (FRAG_B + BL10_B)      // 17408

// Per (tile,lane): {B1.x, B1.y, B2.x, B2.y}  (mma1 / mma2 B fragments)
__device__ uint4 g_Bfrag[NTILES * 32];
// bl10 residuals, float at linear position index (float2-aligned pairs)
__device__ float2 g_bl10[NTILES * 4];
__device__ unsigned long long g_key[ROWS];   // merged via atomicMax

static __device__ __forceinline__ uint32_t h2pack(float x, float y) {
    __half2 h = __halves2half2(__float2half_rn(x), __float2half_rn(y));
    return *(uint32_t*)&h;
}
static __device__ __forceinline__ float hi16(float x) {
    return __half2float(__float2half_rn(x));
}
static __device__ __forceinline__ uint32_t smem_u32(const void* p) {
    uint32_t a;
    asm("{ .reg .u64 t; cvta.to.shared.u64 t, %1; cvt.u32.u64 %0, t; }" : "=r"(a) : "l"(p));
    return a;
}
#define CP_ASYNC16(smem, gmem) \
    asm volatile("cp.async.cg.shared.global [%0], [%1], 16;" :: "r"(smem), "l"(gmem) : "memory")
#define CP_COMMIT() asm volatile("cp.async.commit_group;" ::: "memory")
#define CP_WAIT(n)  asm volatile("cp.async.wait_group %0;" :: "n"(n) : "memory")

// ---- Phase 0: B fragments (packed dual-mma layout), bl10, keys, passthrough ----
__global__ void prep_kernel(const float* __restrict__ index, const float* __restrict__ positions,
                            float* __restrict__ out_pass) {
    int t = blockIdx.x * blockDim.x + threadIdx.x;
    if (t < ROWS) g_key[t] = 0ull;
    if (t < NTILES * 32) {  // B fragments; 4 tig lanes redundantly normalize position
        int lane = t & 31;
        int g = lane >> 2, tig = lane & 3;
        int p = (t >> 5) * 8 + g;
        const float* pp = positions + (size_t)p * ND;
        float v[ND], acc = 0.0f;
#pragma unroll
        for (int d = 0; d < ND; d++) { v[d] = pp[d]; acc = fmaf(v[d], v[d], acc); }
        float nrm = sqrtf(acc);
        float nb[ND], lb[ND];
#pragma unroll
        for (int d = 0; d < ND; d++) {
            nb[d] = v[d] / nrm;
            lb[d] = nb[d] - hi16(nb[d]);
        }
        int k0 = tig * 2;
        // slots k0,k0+1 <= 7 -> always Bh; slots k0+8,k0+9 in 8..15
        int ka = k0 + 8, kb = k0 + 9;
        float b1a = (ka <= 10) ? nb[ka] : lb[ka - 11];
        float b1b = (kb <= 10) ? nb[kb] : lb[kb - 11];
        float b2a = (ka <= 10) ? nb[ka] : lb[ka - 6];
        float b2b = (kb <= 10) ? nb[kb] : lb[kb - 6];
        g_Bfrag[t] = make_uint4(h2pack(nb[k0], nb[k0 + 1]), h2pack(b1a, b1b),
                                h2pack(nb[k0], nb[k0 + 1]), h2pack(b2a, b2b));
    }
    if (t >= NTILES * 32 && t < NTILES * 32 + NPOS) {  // bl10 table
        int p = t - NTILES * 32;
        const float* pp = positions + (size_t)p * ND;
        float v[ND], acc = 0.0f;
#pragma unroll
        for (int d = 0; d < ND; d++) { v[d] = pp[d]; acc = fmaf(v[d], v[d], acc); }
        float b10 = v[10] / sqrtf(acc);
        ((float*)g_bl10)[p] = b10 - hi16(b10);
    }
    if (t < ROWS * ND / 4)  // passthrough (float4)
        ((float4*)out_pass)[t] = ((const float4*)index)[t];
}

static __device__ __forceinline__ void mma16816(float d[4], const uint4& a, uint32_t b0,
                                                uint32_t b1, const float c[4]) {
    asm volatile(
        "mma.sync.aligned.m16n8k16.row.col.f32.f16.f16.f32 "
        "{%0,%1,%2,%3}, {%4,%5,%6,%7}, {%8,%9}, {%10,%11,%12,%13};"
        : "=f"(d[0]), "=f"(d[1]), "=f"(d[2]), "=f"(d[3])
        : "r"(a.x), "r"(a.y), "r"(a.z), "r"(a.w), "r"(b0), "r"(b1),
          "f"(c[0]), "f"(c[1]), "f"(c[2]), "f"(c[3]));
}

// mma1 slot value: k<=10 -> hi(A[k]); else hi(A[k-11])
static __device__ __forceinline__ float v1(const float* A, int k) {
    return (k <= 10) ? A[k] : A[k - 11];   // h2pack rounds to fp16 hi
}
// mma2 slot value: k<=10 -> lo(A[k]); else hi(A[k-6])
static __device__ __forceinline__ float v2(const float* A, int k) {
    return (k <= 10) ? (A[k] - hi16(A[k])) : A[k - 6];
}

// ---- Phase 1: 2-HMMA packed split-fp16 GEMM + scalar d10 correction + argmax.
// blockIdx = (row-block-octet, pos-half); chained accumulators (mma2 C = mma1 D). ----
__global__ void __launch_bounds__(256, 1) argmax_kernel(const float* __restrict__ index) {
    extern __shared__ char dsm[];       // [2][frag 16KB | bl10 1KB]
    __shared__ float sAn[128][16];      // exact normalized A rows

    const int tid = threadIdx.x;
    const int lane = tid & 31;
    const int half = blockIdx.x & 1;
    const int rb8 = blockIdx.x >> 1;
    const int warp = (rb8 << 3) + (tid >> 5);
    const int g = lane >> 2, tig = lane & 3;
    const uint32_t sb0 = smem_u32(dsm);

    const uint4* fsrc = g_Bfrag + (size_t)half * (HTILES * 32);
    const float2* lsrc = g_bl10 + (size_t)half * (HTILES * 4);

    {   // issue chunk 0
#pragma unroll
        for (int i = 0; i < 4; i++) {
            int idx = tid + i * 256;
            CP_ASYNC16(sb0 + (uint32_t)idx * 16u, fsrc + idx);
        }
        if (tid < 64) CP_ASYNC16(sb0 + FRAG_B + (uint32_t)tid * 16u, ((const uint4*)lsrc) + tid);
        CP_COMMIT();
    }

    if (tid < 128) {  // normalize this CTA's 128 A rows (reference op order)
        int row = rb8 * 128 + tid;
        const float* ip = index + (size_t)row * ND;
        float v[ND], acc = 0.0f;
#pragma unroll
        for (int d = 0; d < ND; d++) { v[d] = ip[d]; acc = fmaf(v[d], v[d], acc); }
        float nrm = sqrtf(acc);
#pragma unroll
        for (int d = 0; d < 16; d++) sAn[tid][d] = (d < ND) ? (v[d] / nrm) : 0.0f;
    }
    __syncthreads();

    const int wloc = (tid >> 5) * 16 + g;
    const float* A0 = sAn[wloc];
    const float* A1r = sAn[wloc + 8];
    const float a10r0 = A0[10], a10r1 = A1r[10];

    uint4 Af1, Af2;
    {
        const int k0 = tig * 2, ka = k0 + 8, kb = k0 + 9;
        // low slots (k0,k0+1 <= 7): mma1 = hi, mma2 = lo
        Af1.x = h2pack(A0[k0], A0[k0 + 1]);
        Af1.y = h2pack(A1r[k0], A1r[k0 + 1]);
        Af1.z = h2pack(v1(A0, ka), v1(A0, kb));
        Af1.w = h2pack(v1(A1r, ka), v1(A1r, kb));
        Af2.x = h2pack(A0[k0] - hi16(A0[k0]), A0[k0 + 1] - hi16(A0[k0 + 1]));
        Af2.y = h2pack(A1r[k0] - hi16(A1r[k0]), A1r[k0 + 1] - hi16(A1r[k0 + 1]));
        Af2.z = h2pack(v2(A0, ka), v2(A0, kb));
        Af2.w = h2pack(v2(A1r, ka), v2(A1r, kb));
    }

    float best0 = -1e30f, best1 = -1e30f;
    int bi0 = 0, bi1 = 0;
    const float zc[4] = {0.f, 0.f, 0.f, 0.f};

    for (int c = 0; c < NCHH; c++) {
        if (c + 1 < NCHH) {
            const uint4* src = fsrc + (size_t)(c + 1) * (CTILES * 32);
            uint32_t dst = sb0 + (uint32_t)(((c + 1) & 1) * CHUNK_B);
#pragma unroll
            for (int i = 0; i < 4; i++) {
                int idx = tid + i * 256;
                CP_ASYNC16(dst + (uint32_t)idx * 16u, src + idx);
            }
            if (tid < 64)
                CP_ASYNC16(dst + FRAG_B + (uint32_t)tid * 16u,
                           ((const uint4*)(lsrc + (size_t)(c + 1) * (CTILES * 4))) + tid);
            CP_COMMIT();
            CP_WAIT(1);
        } else {
            CP_WAIT(0);
        }
        __syncthreads();

        const char* cb = dsm + (c & 1) * CHUNK_B;
        const uint4* fr = (const uint4*)cb;
        const float2* bl = (const float2*)(cb + FRAG_B);
        int pbase = half * (HTILES * 8) + c * CTILES * 8 + tig * 2;
#pragma unroll 4
        for (int t = 0; t < CTILES; t++) {
            uint4 F = fr[t * 32 + lane];
            float2 c10 = bl[t * 4 + tig];
            float d[4];
            mma16816(d, Af1, F.x, F.y, zc);
            mma16816(d, Af2, F.z, F.w, d);   // chained accumulator
            float s0 = fmaf(a10r0, c10.x, d[0]);
            float s1 = fmaf(a10r0, c10.y, d[1]);
            float s2 = fmaf(a10r1, c10.x, d[2]);
            float s3 = fmaf(a10r1, c10.y, d[3]);

            int p = pbase + t * 8;
            float m0 = fmaxf(s0, s1);
            if (m0 > best0) { best0 = m0; bi0 = (s1 > s0) ? p + 1 : p; }
            float m1 = fmaxf(s2, s3);
            if (m1 > best1) { best1 = m1; bi1 = (s3 > s2) ? p + 1 : p; }
        }
        __syncthreads();
    }

    unsigned u0 = __float_as_uint(best0);
    u0 = (u0 & 0x80000000u) ? ~u0 : (u0 | 0x80000000u);
    unsigned u1 = __float_as_uint(best1);
    u1 = (u1 & 0x80000000u) ? ~u1 : (u1 | 0x80000000u);
    unsigned long long k0 = ((unsigned long long)u0 << 32) | (unsigned)(NPOS - 1 - bi0);
    unsigned long long k1 = ((unsigned long long)u1 << 32) | (unsigned)(NPOS - 1 - bi1);
#pragma unroll
    for (int s = 1; s <= 2; s <<= 1) {
        unsigned long long o0 = __shfl_xor_sync(0xFFFFFFFFu, k0, s);
        unsigned long long o1 = __shfl_xor_sync(0xFFFFFFFFu, k1, s);
        if (o0 > k0) k0 = o0;
        if (o1 > k1) k1 = o1;
    }
    if (tig == 0) {
        int row0 = warp * 16 + g;
        atomicMax(&g_key[row0], k0);
        atomicMax(&g_key[row0 + 8], k1);
    }
}

// ---- Phase 2: column-owner scatter + int_index write ----
__global__ void __launch_bounds__(512) scatter_kernel(const float* __restrict__ atoms,
                                                      float* __restrict__ out) {
    __shared__ float buf[NS];
    __shared__ int offs[NA];
    const int tid = threadIdx.x;

#pragma unroll 1
    for (int bi = 0; bi < 4; bi++) {
        const int b = blockIdx.x * 4 + bi;
        __syncthreads();
        if (tid < NA) {
            int row = b * NA + tid;
            unsigned long long k = g_key[row];
            int idx = NPOS - 1 - (int)(unsigned)(k & 0xFFFFFFFFull);
            offs[tid] = idx;
            out[row] = (float)idx;
        }
#pragma unroll
        for (int c = 0; c < 8; c++) buf[c * 512 + tid] = 0.0f;
        __syncthreads();

#pragma unroll
        for (int a = 0; a < NA; a++) {
            int off = offs[a];
            int c0 = off >> 9, r = off & 511;
            if (tid >= r)
                buf[c0 * 512 + tid] += __ldg(atoms + a * ATOM + tid - r);
            else
                buf[(c0 + 1) * 512 + tid] += __ldg(atoms + a * ATOM + 512 - r + tid);
        }

        float* ob = out + ROWS + (size_t)b * NS;
#pragma unroll
        for (int c = 0; c < 8; c++) ob[c * 512 + tid] = buf[c * 512 + tid];
    }
}

extern "C" void kernel_launch(void* const* d_in, const int* in_sizes, int n_in,
                              void* d_out, int out_size) {
    const float* index = (const float*)d_in[0];      // (4096, 8, 11)
    const float* positions = (const float*)d_in[1];  // (3584, 11)
    const float* atoms = (const float*)d_in[2];      // (8, 512)
    float* out = (float*)d_out;  // [int_index(32768) | output(16777216) | index(360448)]

    prep_kernel<<<(ROWS * ND / 4 + 255) / 256, 256>>>(
        index, positions, out + ROWS + (size_t)BATCH * NS);

    const int smem = 2 * CHUNK_B;  // 34816 B dynamic
    cudaFuncSetAttribute(argmax_kernel, cudaFuncAttributeMaxDynamicSharedMemorySize, smem);
    argmax_kernel<<<(NRB / 8) * 2, 256, smem>>>(index);

    scatter_kernel<<<BATCH / 4, 512>>>(atoms, out);
}

// round 12
// speedup vs baseline: 3.7860x; 1.0133x over previous
#include <cuda_runtime.h>
#include <cuda_fp16.h>
#include <cstdint>

#define BATCH 4096
#define NA 8
#define ND 11
#define NPOS 3584
#define ATOM 512
#define NS 4096
#define ROWS 32768          // BATCH*NA
#define NTILES 448          // NPOS/8
#define HTILES 224          // tiles per position-half
#define CTILES 32           // tiles per SMEM chunk
#define NCHH 7              // HTILES/CTILES
#define FRAG_B (CTILES * 32 * 16)      // 16384 B fragments per chunk
#define BL10_B (CTILES * 4 * 8)        // 1024 B bl10 per chunk
#define CHUNK_B (FRAG_B + BL10_B)      // 17408

// Per (tile,lane): {B1.x, B1.y, B2.x, B2.y}  (mma1 / mma2 B fragments)
__device__ uint4 g_Bfrag[NTILES * 32];
__device__ float2 g_bl10[NTILES * 4];        // bl10 residuals per position
__device__ unsigned long long g_key[ROWS];   // merged via atomicMax

static __device__ __forceinline__ uint32_t h2pack(float x, float y) {
    __half2 h = __halves2half2(__float2half_rn(x), __float2half_rn(y));
    return *(uint32_t*)&h;
}
static __device__ __forceinline__ float hi16(float x) {
    return __half2float(__float2half_rn(x));
}
static __device__ __forceinline__ uint32_t smem_u32(const void* p) {
    uint32_t a;
    asm("{ .reg .u64 t; cvta.to.shared.u64 t, %1; cvt.u32.u64 %0, t; }" : "=r"(a) : "l"(p));
    return a;
}
#define CP_ASYNC16(smem, gmem) \
    asm volatile("cp.async.cg.shared.global [%0], [%1], 16;" :: "r"(smem), "l"(gmem) : "memory")
#define CP_COMMIT() asm volatile("cp.async.commit_group;" ::: "memory")
#define CP_WAIT(n)  asm volatile("cp.async.wait_group %0;" :: "n"(n) : "memory")

// ---- Phase 0: B fragments (packed dual-mma layout), bl10, zero keys ----
__global__ void prep_kernel(const float* __restrict__ positions) {
    int t = blockIdx.x * blockDim.x + threadIdx.x;
    if (t < ROWS) g_key[t] = 0ull;
    if (t < NTILES * 32) {
        int lane = t & 31;
        int g = lane >> 2, tig = lane & 3;
        int p = (t >> 5) * 8 + g;
        const float* pp = positions + (size_t)p * ND;
        float v[ND], acc = 0.0f;
#pragma unroll
        for (int d = 0; d < ND; d++) { v[d] = pp[d]; acc = fmaf(v[d], v[d], acc); }
        float nrm = sqrtf(acc);
        float nb[ND], lb[ND];
#pragma unroll
        for (int d = 0; d < ND; d++) {
            nb[d] = v[d] / nrm;
            lb[d] = nb[d] - hi16(nb[d]);
        }
        int k0 = tig * 2;
        int ka = k0 + 8, kb = k0 + 9;
        float b1a = (ka <= 10) ? nb[ka] : lb[ka - 11];
        float b1b = (kb <= 10) ? nb[kb] : lb[kb - 11];
        float b2a = (ka <= 10) ? nb[ka] : lb[ka - 6];
        float b2b = (kb <= 10) ? nb[kb] : lb[kb - 6];
        g_Bfrag[t] = make_uint4(h2pack(nb[k0], nb[k0 + 1]), h2pack(b1a, b1b),
                                h2pack(nb[k0], nb[k0 + 1]), h2pack(b2a, b2b));
        if (tig == 0) ((float*)g_bl10)[p] = lb[10];
    }
}

static __device__ __forceinline__ void mma16816(float d[4], const uint4& a, uint32_t b0,
                                                uint32_t b1, const float c[4]) {
    asm volatile(
        "mma.sync.aligned.m16n8k16.row.col.f32.f16.f16.f32 "
        "{%0,%1,%2,%3}, {%4,%5,%6,%7}, {%8,%9}, {%10,%11,%12,%13};"
        : "=f"(d[0]), "=f"(d[1]), "=f"(d[2]), "=f"(d[3])
        : "r"(a.x), "r"(a.y), "r"(a.z), "r"(a.w), "r"(b0), "r"(b1),
          "f"(c[0]), "f"(c[1]), "f"(c[2]), "f"(c[3]));
}

static __device__ __forceinline__ float v1s(const float* A, int k) {
    return (k <= 10) ? A[k] : A[k - 11];
}
static __device__ __forceinline__ float v2s(const float* A, int k) {
    return (k <= 10) ? (A[k] - hi16(A[k])) : A[k - 6];
}
// build the (Af1, Af2) packed fragment pair for rows (R0, R1)
static __device__ __forceinline__ void build_frags(const float* R0, const float* R1, int tig,
                                                   uint4& Af1, uint4& Af2) {
    const int k0 = tig * 2, ka = k0 + 8, kb = k0 + 9;
    Af1.x = h2pack(R0[k0], R0[k0 + 1]);
    Af1.y = h2pack(R1[k0], R1[k0 + 1]);
    Af1.z = h2pack(v1s(R0, ka), v1s(R0, kb));
    Af1.w = h2pack(v1s(R1, ka), v1s(R1, kb));
    Af2.x = h2pack(R0[k0] - hi16(R0[k0]), R0[k0 + 1] - hi16(R0[k0 + 1]));
    Af2.y = h2pack(R1[k0] - hi16(R1[k0]), R1[k0 + 1] - hi16(R1[k0 + 1]));
    Af2.z = h2pack(v2s(R0, ka), v2s(R0, kb));
    Af2.w = h2pack(v2s(R1, ka), v2s(R1, kb));
}

// ---- Phase 1: 2-HMMA packed split-fp16 GEMM, 32 rows/warp, streaming argmax.
// blockIdx = (row-block-256, pos-half); 256 CTAs x 8 warps. ----
__global__ void __launch_bounds__(256, 1) argmax_kernel(const float* __restrict__ index) {
    extern __shared__ char dsm[];       // [2][frag 16KB | bl10 1KB]
    __shared__ float sAn[256][16];      // exact normalized A rows (16 KB)

    const int tid = threadIdx.x;
    const int lane = tid & 31;
    const int half = blockIdx.x & 1;
    const int oct = blockIdx.x >> 1;    // 256-row block id
    const int w = tid >> 5;
    const int g = lane >> 2, tig = lane & 3;
    const uint32_t sb0 = smem_u32(dsm);

    const uint4* fsrc = g_Bfrag + (size_t)half * (HTILES * 32);
    const float2* lsrc = g_bl10 + (size_t)half * (HTILES * 4);

    {   // issue chunk 0
#pragma unroll
        for (int i = 0; i < 4; i++) {
            int idx = tid + i * 256;
            CP_ASYNC16(sb0 + (uint32_t)idx * 16u, fsrc + idx);
        }
        if (tid < 64) CP_ASYNC16(sb0 + FRAG_B + (uint32_t)tid * 16u, ((const uint4*)lsrc) + tid);
        CP_COMMIT();
    }

    {   // normalize this CTA's 256 A rows (reference op order)
        int row = oct * 256 + tid;
        const float* ip = index + (size_t)row * ND;
        float v[ND], acc = 0.0f;
#pragma unroll
        for (int d = 0; d < ND; d++) { v[d] = ip[d]; acc = fmaf(v[d], v[d], acc); }
        float nrm = sqrtf(acc);
#pragma unroll
        for (int d = 0; d < 16; d++) sAn[tid][d] = (d < ND) ? (v[d] / nrm) : 0.0f;
    }
    __syncthreads();

    // local rows: block a = w*32 + {g, g+8}, block b = w*32 + 16 + {g, g+8}
    const float* Ra0 = sAn[w * 32 + g];
    const float* Ra1 = sAn[w * 32 + g + 8];
    const float* Rb0 = sAn[w * 32 + 16 + g];
    const float* Rb1 = sAn[w * 32 + 24 + g];
    const float a10[4] = {Ra0[10], Ra1[10], Rb0[10], Rb1[10]};

    uint4 Af1a, Af2a, Af1b, Af2b;
    build_frags(Ra0, Ra1, tig, Af1a, Af2a);
    build_frags(Rb0, Rb1, tig, Af1b, Af2b);

    float best[4] = {-1e30f, -1e30f, -1e30f, -1e30f};
    int bi[4] = {0, 0, 0, 0};
    const float zc[4] = {0.f, 0.f, 0.f, 0.f};

    for (int c = 0; c < NCHH; c++) {
        if (c + 1 < NCHH) {
            const uint4* src = fsrc + (size_t)(c + 1) * (CTILES * 32);
            uint32_t dst = sb0 + (uint32_t)(((c + 1) & 1) * CHUNK_B);
#pragma unroll
            for (int i = 0; i < 4; i++) {
                int idx = tid + i * 256;
                CP_ASYNC16(dst + (uint32_t)idx * 16u, src + idx);
            }
            if (tid < 64)
                CP_ASYNC16(dst + FRAG_B + (uint32_t)tid * 16u,
                           ((const uint4*)(lsrc + (size_t)(c + 1) * (CTILES * 4))) + tid);
            CP_COMMIT();
            CP_WAIT(1);
        } else {
            CP_WAIT(0);
        }
        __syncthreads();

        const char* cb = dsm + (c & 1) * CHUNK_B;
        const uint4* fr = (const uint4*)cb;
        const float2* bl = (const float2*)(cb + FRAG_B);
        int pbase = half * (HTILES * 8) + c * CTILES * 8 + tig * 2;
#pragma unroll 2
        for (int t = 0; t < CTILES; t++) {
            uint4 F = fr[t * 32 + lane];
            float2 c10 = bl[t * 4 + tig];
            float da[4], db[4];
            mma16816(da, Af1a, F.x, F.y, zc);
            mma16816(da, Af2a, F.z, F.w, da);
            mma16816(db, Af1b, F.x, F.y, zc);
            mma16816(db, Af2b, F.z, F.w, db);
            float s[4][2];
            s[0][0] = fmaf(a10[0], c10.x, da[0]); s[0][1] = fmaf(a10[0], c10.y, da[1]);
            s[1][0] = fmaf(a10[1], c10.x, da[2]); s[1][1] = fmaf(a10[1], c10.y, da[3]);
            s[2][0] = fmaf(a10[2], c10.x, db[0]); s[2][1] = fmaf(a10[2], c10.y, db[1]);
            s[3][0] = fmaf(a10[3], c10.x, db[2]); s[3][1] = fmaf(a10[3], c10.y, db[3]);

            int p = pbase + t * 8;
#pragma unroll
            for (int r = 0; r < 4; r++) {
                float m = fmaxf(s[r][0], s[r][1]);
                if (m > best[r]) { best[r] = m; bi[r] = (s[r][1] > s[r][0]) ? p + 1 : p; }
            }
        }
        __syncthreads();
    }

    // reduce across the 4 tig lanes per row; merge halves via atomicMax
    unsigned long long key[4];
#pragma unroll
    for (int r = 0; r < 4; r++) {
        unsigned u = __float_as_uint(best[r]);
        u = (u & 0x80000000u) ? ~u : (u | 0x80000000u);
        key[r] = ((unsigned long long)u << 32) | (unsigned)(NPOS - 1 - bi[r]);
    }
#pragma unroll
    for (int sft = 1; sft <= 2; sft <<= 1) {
#pragma unroll
        for (int r = 0; r < 4; r++) {
            unsigned long long o = __shfl_xor_sync(0xFFFFFFFFu, key[r], sft);
            if (o > key[r]) key[r] = o;
        }
    }
    if (tig == 0) {
        int rbase = oct * 256 + w * 32;
        atomicMax(&g_key[rbase + g], key[0]);
        atomicMax(&g_key[rbase + g + 8], key[1]);
        atomicMax(&g_key[rbase + 16 + g], key[2]);
        atomicMax(&g_key[rbase + 24 + g], key[3]);
    }
}

// ---- Phase 2: column-owner scatter + int_index write + raw-index passthrough ----
__global__ void __launch_bounds__(512) scatter_kernel(const float* __restrict__ atoms,
                                                      const float* __restrict__ index,
                                                      float* __restrict__ out) {
    __shared__ float buf[NS];
    __shared__ int offs[NA];
    const int tid = threadIdx.x;

    {   // passthrough: first 176 CTAs copy the raw index (90112 float4)
        int i = blockIdx.x * 512 + tid;
        if (i < ROWS * ND / 4)
            ((float4*)(out + ROWS + (size_t)BATCH * NS))[i] = ((const float4*)index)[i];
    }

#pragma unroll 1
    for (int bi = 0; bi < 4; bi++) {
        const int b = blockIdx.x * 4 + bi;
        __syncthreads();
        if (tid < NA) {
            int row = b * NA + tid;
            unsigned long long k = g_key[row];
            int idx = NPOS - 1 - (int)(unsigned)(k & 0xFFFFFFFFull);
            offs[tid] = idx;
            out[row] = (float)idx;
        }
#pragma unroll
        for (int c = 0; c < 8; c++) buf[c * 512 + tid] = 0.0f;
        __syncthreads();

#pragma unroll
        for (int a = 0; a < NA; a++) {
            int off = offs[a];
            int c0 = off >> 9, r = off & 511;
            if (tid >= r)
                buf[c0 * 512 + tid] += __ldg(atoms + a * ATOM + tid - r);
            else
                buf[(c0 + 1) * 512 + tid] += __ldg(atoms + a * ATOM + 512 - r + tid);
        }

        float* ob = out + ROWS + (size_t)b * NS;
#pragma unroll
        for (int c = 0; c < 8; c++) ob[c * 512 + tid] = buf[c * 512 + tid];
    }
}

extern "C" void kernel_launch(void* const* d_in, const int* in_sizes, int n_in,
                              void* d_out, int out_size) {
    const float* index = (const float*)d_in[0];      // (4096, 8, 11)
    const float* positions = (const float*)d_in[1];  // (3584, 11)
    const float* atoms = (const float*)d_in[2];      // (8, 512)
    float* out = (float*)d_out;  // [int_index(32768) | output(16777216) | index(360448)]

    prep_kernel<<<ROWS / 256, 256>>>(positions);

    const int smem = 2 * CHUNK_B;  // 34816 B dynamic (+16 KB static sAn)
    cudaFuncSetAttribute(argmax_kernel, cudaFuncAttributeMaxDynamicSharedMemorySize, smem);
    argmax_kernel<<<(ROWS / 256) * 2, 256, smem>>>(index);

    scatter_kernel<<<BATCH / 4, 512>>>(atoms, index, out);
}